// round 5
// baseline (speedup 1.0000x reference)
#include <cuda_runtime.h>
#include <cstdint>
#include <math.h>

#define TGT   2048
#define NBSZ  2
#define EMB   1024
#define NH    16
#define HD    64
#define NBH   (NBSZ*NH)      // 32
#define MROWS (TGT*NBSZ)     // 4096

// ---------------- scratch (device globals) ---------------------------------
static __device__ float  g_Q  [(size_t)NBH*TGT*HD];
static __device__ float  g_K  [(size_t)NBH*TGT*HD];
static __device__ float  g_Vt [(size_t)NBH*HD*TGT];
static __device__ float  g_attn[(size_t)MROWS*EMB];
static __device__ float2 g_stats[(size_t)NBH*TGT];    // (rowmax, 1/rowsum)

// ---------------- tf32 helpers ---------------------------------------------
__device__ __forceinline__ uint32_t f2tf32(float x){
    uint32_t u; asm("cvt.rna.tf32.f32 %0, %1;" : "=r"(u) : "f"(x)); return u;
}
__device__ __forceinline__ float4 tf4(float4 v){
    v.x = __uint_as_float(f2tf32(v.x));
    v.y = __uint_as_float(f2tf32(v.y));
    v.z = __uint_as_float(f2tf32(v.z));
    v.w = __uint_as_float(f2tf32(v.w));
    return v;
}
__device__ __forceinline__ void mma8(float* c, const uint32_t* a, const uint32_t* b){
    asm volatile("mma.sync.aligned.m16n8k8.row.col.f32.tf32.tf32.f32 "
        "{%0,%1,%2,%3}, {%4,%5,%6,%7}, {%8,%9}, {%0,%1,%2,%3};"
        : "+f"(c[0]), "+f"(c[1]), "+f"(c[2]), "+f"(c[3])
        : "r"(a[0]), "r"(a[1]), "r"(a[2]), "r"(a[3]), "r"(b[0]), "r"(b[1]));
}

// ===========================================================================
// Projection GEMMs: 256 threads, block 128x128, BK=32, warp tile 64x32.
// MODE 0: QKV (scatter to Q/K/Vt), MODE 3: out-proj (+bias -> Cg)
// ===========================================================================
#define LDSROW 36
#define G_A1   4608
#define G_B0   9216
#define GEMM_SMEM_BYTES (18432*4)   // 73728

template<int MODE>
__global__ __launch_bounds__(256)
void mma_gemm(const float* __restrict__ Ag, const float* __restrict__ Bg,
              float* __restrict__ Cg, const float* __restrict__ biasg)
{
    constexpr int KC = 1024 / 32;

    extern __shared__ float sm[];
    const int tid = threadIdx.x, lane = tid & 31, wid = tid >> 5;
    const int wm = wid & 1, wn = wid >> 1;          // 2(m) x 4(n)
    const int lr = lane >> 2, lc = lane & 3;
    const int bm = blockIdx.y * 128, bn = blockIdx.x * 128;

    const float* A = (MODE == 0) ? Ag : g_attn;
    const float* B = Bg;
    const int lda = EMB, ldb = EMB;

    float acc[4][4][4];
    #pragma unroll
    for (int i=0;i<4;i++) for (int j=0;j<4;j++) for (int k=0;k<4;k++) acc[i][j][k]=0.f;

    float4 stA[4], stB[4];
    auto ldg_chunk = [&](int k0){
        #pragma unroll
        for (int t=0;t<4;t++){
            int fi = tid + t*256, r = fi>>3, c4 = fi&7;
            stA[t] = *(const float4*)(A + (size_t)(bm+r)*lda + k0 + c4*4);
            stB[t] = *(const float4*)(B + (size_t)(bn+r)*ldb + k0 + c4*4);
        }
    };
    auto sts_chunk = [&](int buf){
        float* a = sm + buf*G_A1;
        float* b = sm + G_B0 + buf*G_A1;
        #pragma unroll
        for (int t=0;t<4;t++){
            int fi = tid + t*256, r = fi>>3, c4 = fi&7;
            *(float4*)(a + r*LDSROW + c4*4) = tf4(stA[t]);
            *(float4*)(b + r*LDSROW + c4*4) = tf4(stB[t]);
        }
    };

    ldg_chunk(0); sts_chunk(0); __syncthreads();

    for (int c = 0; c < KC; c++) {
        const int buf = c & 1;
        if (c + 1 < KC) ldg_chunk((c+1)*32);
        const float* Ab = sm + buf*G_A1;
        const float* Bb = sm + G_B0 + buf*G_A1;
        #pragma unroll
        for (int ks = 0; ks < 4; ks++) {
            uint32_t af[4][4], bf[4][2];
            #pragma unroll
            for (int mt=0; mt<4; mt++){
                const float* p = Ab + (wm*64 + mt*16 + lr)*LDSROW + ks*8 + lc;
                af[mt][0]=__float_as_uint(p[0]); af[mt][1]=__float_as_uint(p[8*LDSROW]);
                af[mt][2]=__float_as_uint(p[4]); af[mt][3]=__float_as_uint(p[8*LDSROW+4]);
            }
            #pragma unroll
            for (int nt=0; nt<4; nt++){
                const float* p = Bb + (wn*32 + nt*8 + lr)*LDSROW + ks*8 + lc;
                bf[nt][0]=__float_as_uint(p[0]); bf[nt][1]=__float_as_uint(p[4]);
            }
            #pragma unroll
            for (int mt=0; mt<4; mt++)
                #pragma unroll
                for (int nt=0; nt<4; nt++)
                    mma8(acc[mt][nt], af[mt], bf[nt]);
        }
        if (c + 1 < KC) { sts_chunk((c+1)&1); __syncthreads(); }
    }

    float bias0[4], bias1[4];
    #pragma unroll
    for (int nt=0; nt<4; nt++){
        int n = bn + wn*32 + nt*8 + lc*2;
        bias0[nt] = biasg[n]; bias1[nt] = biasg[n+1];
    }

    #pragma unroll
    for (int mt=0; mt<4; mt++)
    #pragma unroll
    for (int half=0; half<2; half++){
        const int m = bm + wm*64 + mt*16 + half*8 + lr;
        if (MODE == 0) {
            const int t = m >> 1, b = m & 1;
            #pragma unroll
            for (int nt=0; nt<4; nt++){
                const int n = bn + wn*32 + nt*8 + lc*2;
                float v0 = acc[mt][nt][half*2+0] + bias0[nt];
                float v1 = acc[mt][nt][half*2+1] + bias1[nt];
                const int which = n >> 10, e = n & 1023, h = e >> 6, d = e & 63;
                const int bh = b*NH + h;
                if (which == 0) {
                    *(float2*)&g_Q[((size_t)bh*TGT + t)*HD + d] = make_float2(v0*0.125f, v1*0.125f);
                } else if (which == 1) {
                    *(float2*)&g_K[((size_t)bh*TGT + t)*HD + d] = make_float2(v0, v1);
                } else {
                    g_Vt[((size_t)bh*HD + d    )*TGT + t] = v0;
                    g_Vt[((size_t)bh*HD + d + 1)*TGT + t] = v1;
                }
            }
        } else {
            float* dst = Cg + (size_t)m*EMB;
            #pragma unroll
            for (int nt=0; nt<4; nt++){
                const int n = bn + wn*32 + nt*8 + lc*2;
                *(float2*)&dst[n] = make_float2(acc[mt][nt][half*2] + bias0[nt],
                                                acc[mt][nt][half*2+1] + bias1[nt]);
            }
        }
    }
}

// ===========================================================================
// Flash attention: 256 threads, q-tile 128, warp owns 16 q-rows, k-chunk 64.
// SMEM floats: QB[2][128][36]@0, KB[2][64][36]@9216, VB[2][64][36]@13824,
//              PB[2][128][36]@18432 -> 27648 floats = 110592 B.
// ===========================================================================
#define FA_SMEM_BYTES (27648*4)

__global__ __launch_bounds__(256)
void flash_attn_k()
{
    extern __shared__ float sm[];
    const int tid = threadIdx.x, lane = tid & 31, w = tid >> 5;
    const int lr = lane >> 2, lc = lane & 3;
    const int qt = blockIdx.x, bh = blockIdx.y;
    const int b = bh >> 4, h = bh & 15;
    const int qbase = qt * 128;

    const float* Qg = g_Q  + (size_t)bh*TGT*HD;
    const float* Kg = g_K  + (size_t)bh*TGT*HD;
    const float* Vg = g_Vt + (size_t)bh*HD*TGT;

    float* QB = sm;
    float* KB = sm + 9216;
    float* VB = sm + 13824;
    float* PB = sm + 18432;

    #pragma unroll
    for (int i=0;i<8;i++){
        int fi = tid + i*256, r = fi>>4, c4 = fi&15;
        float4 v = tf4(*(const float4*)(Qg + (size_t)(qbase+r)*HD + c4*4));
        *(float4*)(QB + (c4>=8)*4608 + r*36 + (c4&7)*4) = v;
    }

    float acc_o[8][4];
    #pragma unroll
    for (int j=0;j<8;j++) for (int k=0;k<4;k++) acc_o[j][k]=0.f;
    float m_r[2] = {-1e30f,-1e30f};
    float l_r[2] = {0.f,0.f};

    for (int kc = 0; kc < TGT/64; kc++) {
        #pragma unroll
        for (int i=0;i<4;i++){
            int fi = tid + i*256, r = fi>>4, c4 = fi&15;
            float4 v = tf4(*(const float4*)(Kg + (size_t)(kc*64+r)*HD + c4*4));
            *(float4*)(KB + (c4>=8)*2304 + r*36 + (c4&7)*4) = v;
        }
        #pragma unroll
        for (int i=0;i<4;i++){
            int fi = tid + i*256, d = fi>>4, c4 = fi&15;
            float4 v = tf4(*(const float4*)(Vg + (size_t)d*TGT + kc*64 + c4*4));
            *(float4*)(VB + (c4>=8)*2304 + d*36 + (c4&7)*4) = v;
        }
        __syncthreads();

        // S = Q K^T  (warp rows w*16.., all 64 cols)
        float s[8][4];
        #pragma unroll
        for (int j=0;j<8;j++) for (int k=0;k<4;k++) s[j][k]=0.f;
        #pragma unroll
        for (int ks=0; ks<8; ks++){
            const int hb = ks>>2, ko = (ks&3)*8;
            uint32_t af[4], bf[8][2];
            {
                const float* p = QB + hb*4608 + (w*16 + lr)*36 + ko + lc;
                af[0]=__float_as_uint(p[0]); af[1]=__float_as_uint(p[8*36]);
                af[2]=__float_as_uint(p[4]); af[3]=__float_as_uint(p[8*36+4]);
            }
            #pragma unroll
            for (int nt=0; nt<8; nt++){
                const float* p = KB + hb*2304 + (nt*8 + lr)*36 + ko + lc;
                bf[nt][0]=__float_as_uint(p[0]); bf[nt][1]=__float_as_uint(p[4]);
            }
            #pragma unroll
            for (int nt=0; nt<8; nt++)
                mma8(s[nt], af, bf[nt]);
        }

        // online softmax
        #pragma unroll
        for (int hf=0; hf<2; hf++){
            float cm = -1e30f;
            #pragma unroll
            for (int nt=0; nt<8; nt++)
                cm = fmaxf(cm, fmaxf(s[nt][hf*2], s[nt][hf*2+1]));
            cm = fmaxf(cm, __shfl_xor_sync(0xffffffffu, cm, 1));
            cm = fmaxf(cm, __shfl_xor_sync(0xffffffffu, cm, 2));
            const float mn = fmaxf(m_r[hf], cm);
            const float sc = __expf(m_r[hf] - mn);
            float cs = 0.f;
            #pragma unroll
            for (int nt=0; nt<8; nt++){
                float e0 = __expf(s[nt][hf*2]   - mn);
                float e1 = __expf(s[nt][hf*2+1] - mn);
                s[nt][hf*2] = e0; s[nt][hf*2+1] = e1;
                cs += e0 + e1;
            }
            cs += __shfl_xor_sync(0xffffffffu, cs, 1);
            cs += __shfl_xor_sync(0xffffffffu, cs, 2);
            l_r[hf] = l_r[hf]*sc + cs;
            m_r[hf] = mn;
            #pragma unroll
            for (int nt=0; nt<8; nt++){
                acc_o[nt][hf*2]   *= sc;
                acc_o[nt][hf*2+1] *= sc;
            }
        }

        // P -> smem (warp-private rows)
        #pragma unroll
        for (int nt=0; nt<8; nt++)
        #pragma unroll
        for (int hf=0; hf<2; hf++){
            const int row = w*16 + hf*8 + lr;
            float2 pv;
            pv.x = __uint_as_float(f2tf32(s[nt][hf*2]));
            pv.y = __uint_as_float(f2tf32(s[nt][hf*2+1]));
            *(float2*)(PB + (nt>>2)*4608 + row*36 + (nt&3)*8 + lc*2) = pv;
        }
        __syncwarp();

        // O += P V
        #pragma unroll
        for (int ks=0; ks<8; ks++){
            const int hb = ks>>2, ko = (ks&3)*8;
            uint32_t af[4], bf[8][2];
            {
                const float* p = PB + hb*4608 + (w*16 + lr)*36 + ko + lc;
                af[0]=__float_as_uint(p[0]); af[1]=__float_as_uint(p[8*36]);
                af[2]=__float_as_uint(p[4]); af[3]=__float_as_uint(p[8*36+4]);
            }
            #pragma unroll
            for (int nt=0; nt<8; nt++){
                const float* p = VB + hb*2304 + (nt*8 + lr)*36 + ko + lc;
                bf[nt][0]=__float_as_uint(p[0]); bf[nt][1]=__float_as_uint(p[4]);
            }
            #pragma unroll
            for (int nt=0; nt<8; nt++)
                mma8(acc_o[nt], af, bf[nt]);
        }
        __syncthreads();
    }

    #pragma unroll
    for (int hf=0; hf<2; hf++){
        const float invl = 1.0f / l_r[hf];
        const int q = qbase + w*16 + hf*8 + lr;
        float* dst = g_attn + ((size_t)q*NBSZ + b)*EMB + h*HD;
        #pragma unroll
        for (int nt=0; nt<8; nt++)
            *(float2*)(dst + nt*8 + lc*2) =
                make_float2(acc_o[nt][hf*2]*invl, acc_o[nt][hf*2+1]*invl);
        if (lc == 0)
            g_stats[(size_t)bh*TGT + q] = make_float2(m_r[hf], invl);
    }
}

// ===========================================================================
// avg weights: 256 threads, block out 128(q) x 64(k), warp tile 32x32.
// Recomputes S per head (bitwise-identical mma chain), applies stats.
// SMEM: QB[2][128][36]@0, KB[2][64][36]@9216 -> 13824 floats = 55296 B.
// ===========================================================================
#define AVG_SMEM_BYTES (13824*4)

__global__ __launch_bounds__(256)
void avg_attn_k(float* __restrict__ avg_out)
{
    extern __shared__ float sm[];
    float* QB = sm;
    float* KB = sm + 9216;
    const int tid = threadIdx.x, lane = tid & 31, wid = tid >> 5;
    const int wm = wid & 3, wn = wid >> 2;          // 4(q) x 2(k)
    const int lr = lane >> 2, lc = lane & 3;
    const int kt = blockIdx.x, qt = blockIdx.y, b = blockIdx.z;

    float acc[2][4][4];
    #pragma unroll
    for (int i=0;i<2;i++) for (int j=0;j<4;j++) for (int k=0;k<4;k++) acc[i][j][k]=0.f;

    for (int h = 0; h < NH; h++) {
        const int bh = b*NH + h;
        const float* Qg = g_Q + (size_t)bh*TGT*HD;
        const float* Kg = g_K + (size_t)bh*TGT*HD;
        #pragma unroll
        for (int i=0;i<8;i++){
            int fi = tid + i*256, r = fi>>4, c4 = fi&15;
            float4 v = tf4(*(const float4*)(Qg + (size_t)(qt*128+r)*HD + c4*4));
            *(float4*)(QB + (c4>=8)*4608 + r*36 + (c4&7)*4) = v;
        }
        #pragma unroll
        for (int i=0;i<4;i++){
            int fi = tid + i*256, r = fi>>4, c4 = fi&15;
            float4 v = tf4(*(const float4*)(Kg + (size_t)(kt*64+r)*HD + c4*4));
            *(float4*)(KB + (c4>=8)*2304 + r*36 + (c4&7)*4) = v;
        }
        __syncthreads();

        float s[2][4][4];
        #pragma unroll
        for (int i=0;i<2;i++) for (int j=0;j<4;j++) for (int k=0;k<4;k++) s[i][j][k]=0.f;
        #pragma unroll
        for (int ks=0; ks<8; ks++){
            const int hb = ks>>2, ko = (ks&3)*8;
            uint32_t af[2][4], bf[4][2];
            #pragma unroll
            for (int mt=0; mt<2; mt++){
                const float* p = QB + hb*4608 + (wm*32 + mt*16 + lr)*36 + ko + lc;
                af[mt][0]=__float_as_uint(p[0]); af[mt][1]=__float_as_uint(p[8*36]);
                af[mt][2]=__float_as_uint(p[4]); af[mt][3]=__float_as_uint(p[8*36+4]);
            }
            #pragma unroll
            for (int nt=0; nt<4; nt++){
                const float* p = KB + hb*2304 + (wn*32 + nt*8 + lr)*36 + ko + lc;
                bf[nt][0]=__float_as_uint(p[0]); bf[nt][1]=__float_as_uint(p[4]);
            }
            #pragma unroll
            for (int mt=0; mt<2; mt++)
                #pragma unroll
                for (int nt=0; nt<4; nt++)
                    mma8(s[mt][nt], af[mt], bf[nt]);
        }

        #pragma unroll
        for (int mt=0; mt<2; mt++)
        #pragma unroll
        for (int hf=0; hf<2; hf++){
            const int q = qt*128 + wm*32 + mt*16 + hf*8 + lr;
            const float2 st = g_stats[(size_t)bh*TGT + q];
            #pragma unroll
            for (int nt=0; nt<4; nt++){
                acc[mt][nt][hf*2]   += __expf(s[mt][nt][hf*2]   - st.x) * st.y;
                acc[mt][nt][hf*2+1] += __expf(s[mt][nt][hf*2+1] - st.x) * st.y;
            }
        }
        __syncthreads();
    }

    const float invH = 1.0f / NH;
    #pragma unroll
    for (int mt=0; mt<2; mt++)
    #pragma unroll
    for (int hf=0; hf<2; hf++){
        const int q = qt*128 + wm*32 + mt*16 + hf*8 + lr;
        float* dst = avg_out + ((size_t)b*TGT + q)*TGT + kt*64 + wn*32;
        #pragma unroll
        for (int nt=0; nt<4; nt++)
            *(float2*)(dst + nt*8 + lc*2) =
                make_float2(acc[mt][nt][hf*2]*invH, acc[mt][nt][hf*2+1]*invH);
    }
}

// ---------------------------------------------------------------------------
extern "C" void kernel_launch(void* const* d_in, const int* in_sizes, int n_in,
                              void* d_out, int out_size)
{
    const float* query = (const float*)d_in[0];
    const float* w_in  = (const float*)d_in[1];
    const float* b_in  = (const float*)d_in[2];
    const float* w_out = (const float*)d_in[3];
    const float* b_out = (const float*)d_in[4];

    float* out      = (float*)d_out;
    float* attn_out = out;                           // [T,B,E]
    float* avg_out  = out + (size_t)TGT*NBSZ*EMB;    // [B,T,T]

    cudaFuncSetAttribute(mma_gemm<0>,  cudaFuncAttributeMaxDynamicSharedMemorySize, GEMM_SMEM_BYTES);
    cudaFuncSetAttribute(mma_gemm<3>,  cudaFuncAttributeMaxDynamicSharedMemorySize, GEMM_SMEM_BYTES);
    cudaFuncSetAttribute(flash_attn_k, cudaFuncAttributeMaxDynamicSharedMemorySize, FA_SMEM_BYTES);
    cudaFuncSetAttribute(avg_attn_k,   cudaFuncAttributeMaxDynamicSharedMemorySize, AVG_SMEM_BYTES);

    // 1. QKV projection
    mma_gemm<0><<<dim3(3*EMB/128, MROWS/128), 256, GEMM_SMEM_BYTES>>>(query, w_in, nullptr, b_in);

    // 2. Flash attention (fused scores+softmax+PV), writes stats
    flash_attn_k<<<dim3(TGT/128, NBH), 256, FA_SMEM_BYTES>>>();

    // 3. Averaged attention weights
    avg_attn_k<<<dim3(TGT/64, TGT/128, NBSZ), 256, AVG_SMEM_BYTES>>>(avg_out);

    // 4. Output projection
    mma_gemm<3><<<dim3(EMB/128, MROWS/128), 256, GEMM_SMEM_BYTES>>>(nullptr, w_out, attn_out, b_out);
}

// round 6
// speedup vs baseline: 1.0216x; 1.0216x over previous
#include <cuda_runtime.h>
#include <cstdint>
#include <math.h>

#define TGT   2048
#define NBSZ  2
#define EMB   1024
#define NH    16
#define HD    64
#define NBH   (NBSZ*NH)      // 32
#define MROWS (TGT*NBSZ)     // 4096

// ---------------- scratch (device globals) ---------------------------------
static __device__ float  g_Q  [(size_t)NBH*TGT*HD];     // pre-rounded tf32
static __device__ float  g_K  [(size_t)NBH*TGT*HD];     // pre-rounded tf32
static __device__ float  g_Vt [(size_t)NBH*HD*TGT];     // pre-rounded tf32
static __device__ float  g_attn[(size_t)MROWS*EMB];     // pre-rounded tf32
static __device__ float2 g_stats[(size_t)NBH*TGT];      // (rowmax, 1/rowsum)
static __device__ float  g_qc [(size_t)MROWS*EMB];      // query, tf32
static __device__ float  g_wic[(size_t)3*EMB*EMB];      // in_proj_w, tf32
static __device__ float  g_woc[(size_t)EMB*EMB];        // out_w, tf32

// ---------------- helpers ---------------------------------------------------
__device__ __forceinline__ uint32_t f2tf32(float x){
    uint32_t u; asm("cvt.rna.tf32.f32 %0, %1;" : "=r"(u) : "f"(x)); return u;
}
__device__ __forceinline__ float rt(float x){ return __uint_as_float(f2tf32(x)); }
__device__ __forceinline__ float4 tf4(float4 v){
    v.x = rt(v.x); v.y = rt(v.y); v.z = rt(v.z); v.w = rt(v.w); return v;
}
__device__ __forceinline__ void mma8(float* c, const uint32_t* a, const uint32_t* b){
    asm volatile("mma.sync.aligned.m16n8k8.row.col.f32.tf32.tf32.f32 "
        "{%0,%1,%2,%3}, {%4,%5,%6,%7}, {%8,%9}, {%0,%1,%2,%3};"
        : "+f"(c[0]), "+f"(c[1]), "+f"(c[2]), "+f"(c[3])
        : "r"(a[0]), "r"(a[1]), "r"(a[2]), "r"(a[3]), "r"(b[0]), "r"(b[1]));
}
__device__ __forceinline__ uint32_t smem_u32(const void* p){
    uint32_t a; asm("{ .reg .u64 t; cvta.to.shared.u64 t, %1; cvt.u32.u64 %0, t; }":"=r"(a):"l"(p));
    return a;
}
__device__ __forceinline__ void cpa16(uint32_t s, const void* g){
    asm volatile("cp.async.cg.shared.global [%0], [%1], 16;" :: "r"(s), "l"(g) : "memory");
}
#define CP_COMMIT() asm volatile("cp.async.commit_group;" ::: "memory")
#define CP_WAIT(n)  asm volatile("cp.async.wait_group %0;" :: "n"(n) : "memory")

// ---------------- pre-round inputs to tf32 ----------------------------------
__global__ void preround_k(const float4* __restrict__ src, float4* __restrict__ dst, int n4)
{
    int i = blockIdx.x*blockDim.x + threadIdx.x;
    if (i < n4) dst[i] = tf4(src[i]);
}

// ===========================================================================
// Projection GEMMs: block 256(M)x128(N), 256 thr, 8 warps, warp tile 64x64.
// Operands pre-rounded tf32 in global; pure cp.async double-buffered pipe.
// MODE 0: QKV (A=g_qc, B=g_wic, scatter rounded Q/K/Vt)
// MODE 3: out-proj (A=g_attn, B=g_woc, +bias -> Cg, full f32 out)
// SMEM floats: A0@0(9216) A1@9216 B0@18432(4608) B1@23040 -> 27648 (110592 B)
// ===========================================================================
#define GEMM_SMEM_BYTES (27648*4)

template<int MODE>
__global__ __launch_bounds__(256)
void mma_gemm(float* __restrict__ Cg, const float* __restrict__ biasg)
{
    constexpr int KC = 32;
    extern __shared__ float sm[];
    const uint32_t sb = smem_u32(sm);
    const int tid = threadIdx.x, lane = tid & 31, wid = tid >> 5;
    const int wm = wid & 3, wn = wid >> 2;          // 4(m) x 2(n)
    const int lr = lane >> 2, lc = lane & 3;
    const int bm = blockIdx.y * 256, bn = blockIdx.x * 128;

    const float* A = (MODE == 0) ? g_qc  : g_attn;
    const float* B = (MODE == 0) ? g_wic : g_woc;

    float acc[4][8][4];
    #pragma unroll
    for (int i=0;i<4;i++) for (int j=0;j<8;j++) for (int k=0;k<4;k++) acc[i][j][k]=0.f;

    auto issue = [&](int c){
        const int k0 = c*32, buf = c&1;
        const uint32_t ab = sb + (buf*9216)*4;
        const uint32_t bb = sb + (18432 + buf*4608)*4;
        #pragma unroll
        for (int i=0;i<8;i++){
            int fi = tid + i*256, r = fi>>3, c4 = fi&7;
            cpa16(ab + (r*36 + c4*4)*4, A + (size_t)(bm+r)*EMB + k0 + c4*4);
        }
        #pragma unroll
        for (int i=0;i<4;i++){
            int fi = tid + i*256, r = fi>>3, c4 = fi&7;
            cpa16(bb + (r*36 + c4*4)*4, B + (size_t)(bn+r)*EMB + k0 + c4*4);
        }
        CP_COMMIT();
    };

    issue(0);
    for (int c = 0; c < KC; c++) {
        if (c + 1 < KC) { issue(c+1); CP_WAIT(1); } else { CP_WAIT(0); }
        __syncthreads();
        const float* Ab = sm + (c&1)*9216;
        const float* Bb = sm + 18432 + (c&1)*4608;
        #pragma unroll
        for (int ks = 0; ks < 4; ks++) {
            uint32_t af[4][4], bf[8][2];
            #pragma unroll
            for (int mt=0; mt<4; mt++){
                const float* p = Ab + (wm*64 + mt*16 + lr)*36 + ks*8 + lc;
                af[mt][0]=__float_as_uint(p[0]); af[mt][1]=__float_as_uint(p[8*36]);
                af[mt][2]=__float_as_uint(p[4]); af[mt][3]=__float_as_uint(p[8*36+4]);
            }
            #pragma unroll
            for (int nt=0; nt<8; nt++){
                const float* p = Bb + (wn*64 + nt*8 + lr)*36 + ks*8 + lc;
                bf[nt][0]=__float_as_uint(p[0]); bf[nt][1]=__float_as_uint(p[4]);
            }
            #pragma unroll
            for (int mt=0; mt<4; mt++)
                #pragma unroll
                for (int nt=0; nt<8; nt++)
                    mma8(acc[mt][nt], af[mt], bf[nt]);
        }
        __syncthreads();
    }

    float bias0[8], bias1[8];
    #pragma unroll
    for (int nt=0; nt<8; nt++){
        int n = bn + wn*64 + nt*8 + lc*2;
        bias0[nt] = biasg[n]; bias1[nt] = biasg[n+1];
    }

    #pragma unroll
    for (int mt=0; mt<4; mt++)
    #pragma unroll
    for (int hf=0; hf<2; hf++){
        const int m = bm + wm*64 + mt*16 + hf*8 + lr;
        if (MODE == 0) {
            const int t = m >> 1, b = m & 1;
            #pragma unroll
            for (int nt=0; nt<8; nt++){
                const int n = bn + wn*64 + nt*8 + lc*2;
                float v0 = acc[mt][nt][hf*2+0] + bias0[nt];
                float v1 = acc[mt][nt][hf*2+1] + bias1[nt];
                const int which = n >> 10, e = n & 1023, h = e >> 6, d = e & 63;
                const int bh = b*NH + h;
                if (which == 0) {
                    *(float2*)&g_Q[((size_t)bh*TGT + t)*HD + d] =
                        make_float2(rt(v0*0.125f), rt(v1*0.125f));
                } else if (which == 1) {
                    *(float2*)&g_K[((size_t)bh*TGT + t)*HD + d] = make_float2(rt(v0), rt(v1));
                } else {
                    g_Vt[((size_t)bh*HD + d    )*TGT + t] = rt(v0);
                    g_Vt[((size_t)bh*HD + d + 1)*TGT + t] = rt(v1);
                }
            }
        } else {
            float* dst = Cg + (size_t)m*EMB;
            #pragma unroll
            for (int nt=0; nt<8; nt++){
                const int n = bn + wn*64 + nt*8 + lc*2;
                *(float2*)&dst[n] = make_float2(acc[mt][nt][hf*2] + bias0[nt],
                                                acc[mt][nt][hf*2+1] + bias1[nt]);
            }
        }
    }
}

// ===========================================================================
// Flash attention: 256 thr, q-tile 128 (warp=16 rows), k-chunk 64,
// cp.async + double-buffered K/V.
// SMEM floats: QB@0(9216) K0@9216 V0@13824 K1@18432 V1@23040 PB@27648(9216)
//              -> 36864 floats = 147456 B
// ===========================================================================
#define FA_SMEM_BYTES (36864*4)

__global__ __launch_bounds__(256)
void flash_attn_k()
{
    extern __shared__ float sm[];
    const uint32_t sb = smem_u32(sm);
    const int tid = threadIdx.x, lane = tid & 31, w = tid >> 5;
    const int lr = lane >> 2, lc = lane & 3;
    const int qt = blockIdx.x, bh = blockIdx.y;
    const int b = bh >> 4, h = bh & 15;
    const int qbase = qt * 128;

    const float* Qg = g_Q  + (size_t)bh*TGT*HD;
    const float* Kg = g_K  + (size_t)bh*TGT*HD;
    const float* Vg = g_Vt + (size_t)bh*HD*TGT;

    float* QB = sm;
    float* PB = sm + 27648;

    auto issue_kv = [&](int kc){
        const int buf = kc & 1;
        const uint32_t kb = sb + (9216  + buf*9216)*4;
        const uint32_t vb = sb + (13824 + buf*9216)*4;
        #pragma unroll
        for (int i=0;i<4;i++){
            int fi = tid + i*256, r = fi>>4, c4 = fi&15;
            cpa16(kb + ((c4>=8)*2304 + r*36 + (c4&7)*4)*4,
                  Kg + (size_t)(kc*64+r)*HD + c4*4);
        }
        #pragma unroll
        for (int i=0;i<4;i++){
            int fi = tid + i*256, d = fi>>4, c4 = fi&15;
            cpa16(vb + ((c4>=8)*2304 + d*36 + (c4&7)*4)*4,
                  Vg + (size_t)d*TGT + kc*64 + c4*4);
        }
        CP_COMMIT();
    };

    // prologue: Q tile + KV chunk 0
    #pragma unroll
    for (int i=0;i<8;i++){
        int fi = tid + i*256, r = fi>>4, c4 = fi&15;
        cpa16(sb + ((c4>=8)*4608 + r*36 + (c4&7)*4)*4,
              Qg + (size_t)(qbase+r)*HD + c4*4);
    }
    issue_kv(0);

    float acc_o[8][4];
    #pragma unroll
    for (int j=0;j<8;j++) for (int k=0;k<4;k++) acc_o[j][k]=0.f;
    float m_r[2] = {-1e30f,-1e30f};
    float l_r[2] = {0.f,0.f};

    for (int kc = 0; kc < TGT/64; kc++) {
        if (kc + 1 < TGT/64) { issue_kv(kc+1); CP_WAIT(1); } else { CP_WAIT(0); }
        __syncthreads();
        const float* KB = sm + 9216  + (kc&1)*9216;
        const float* VB = sm + 13824 + (kc&1)*9216;

        // S = Q K^T
        float s[8][4];
        #pragma unroll
        for (int j=0;j<8;j++) for (int k=0;k<4;k++) s[j][k]=0.f;
        #pragma unroll
        for (int ks=0; ks<8; ks++){
            const int hb = ks>>2, ko = (ks&3)*8;
            uint32_t af[4], bf[8][2];
            {
                const float* p = QB + hb*4608 + (w*16 + lr)*36 + ko + lc;
                af[0]=__float_as_uint(p[0]); af[1]=__float_as_uint(p[8*36]);
                af[2]=__float_as_uint(p[4]); af[3]=__float_as_uint(p[8*36+4]);
            }
            #pragma unroll
            for (int nt=0; nt<8; nt++){
                const float* p = KB + hb*2304 + (nt*8 + lr)*36 + ko + lc;
                bf[nt][0]=__float_as_uint(p[0]); bf[nt][1]=__float_as_uint(p[4]);
            }
            #pragma unroll
            for (int nt=0; nt<8; nt++)
                mma8(s[nt], af, bf[nt]);
        }

        // online softmax
        #pragma unroll
        for (int hf=0; hf<2; hf++){
            float cm = -1e30f;
            #pragma unroll
            for (int nt=0; nt<8; nt++)
                cm = fmaxf(cm, fmaxf(s[nt][hf*2], s[nt][hf*2+1]));
            cm = fmaxf(cm, __shfl_xor_sync(0xffffffffu, cm, 1));
            cm = fmaxf(cm, __shfl_xor_sync(0xffffffffu, cm, 2));
            const float mn = fmaxf(m_r[hf], cm);
            const float sc = __expf(m_r[hf] - mn);
            float cs = 0.f;
            #pragma unroll
            for (int nt=0; nt<8; nt++){
                float e0 = __expf(s[nt][hf*2]   - mn);
                float e1 = __expf(s[nt][hf*2+1] - mn);
                s[nt][hf*2] = e0; s[nt][hf*2+1] = e1;
                cs += e0 + e1;
            }
            cs += __shfl_xor_sync(0xffffffffu, cs, 1);
            cs += __shfl_xor_sync(0xffffffffu, cs, 2);
            l_r[hf] = l_r[hf]*sc + cs;
            m_r[hf] = mn;
            #pragma unroll
            for (int nt=0; nt<8; nt++){
                acc_o[nt][hf*2]   *= sc;
                acc_o[nt][hf*2+1] *= sc;
            }
        }

        // P -> smem (warp-private rows)
        #pragma unroll
        for (int nt=0; nt<8; nt++)
        #pragma unroll
        for (int hf=0; hf<2; hf++){
            const int row = w*16 + hf*8 + lr;
            float2 pv = make_float2(rt(s[nt][hf*2]), rt(s[nt][hf*2+1]));
            *(float2*)(PB + (nt>>2)*4608 + row*36 + (nt&3)*8 + lc*2) = pv;
        }
        __syncwarp();

        // O += P V
        #pragma unroll
        for (int ks=0; ks<8; ks++){
            const int hb = ks>>2, ko = (ks&3)*8;
            uint32_t af[4], bf[8][2];
            {
                const float* p = PB + hb*4608 + (w*16 + lr)*36 + ko + lc;
                af[0]=__float_as_uint(p[0]); af[1]=__float_as_uint(p[8*36]);
                af[2]=__float_as_uint(p[4]); af[3]=__float_as_uint(p[8*36+4]);
            }
            #pragma unroll
            for (int nt=0; nt<8; nt++){
                const float* p = VB + hb*2304 + (nt*8 + lr)*36 + ko + lc;
                bf[nt][0]=__float_as_uint(p[0]); bf[nt][1]=__float_as_uint(p[4]);
            }
            #pragma unroll
            for (int nt=0; nt<8; nt++)
                mma8(acc_o[nt], af, bf[nt]);
        }
        __syncthreads();
    }

    #pragma unroll
    for (int hf=0; hf<2; hf++){
        const float invl = 1.0f / l_r[hf];
        const int q = qbase + w*16 + hf*8 + lr;
        float* dst = g_attn + ((size_t)q*NBSZ + b)*EMB + h*HD;
        #pragma unroll
        for (int nt=0; nt<8; nt++)
            *(float2*)(dst + nt*8 + lc*2) =
                make_float2(rt(acc_o[nt][hf*2]*invl), rt(acc_o[nt][hf*2+1]*invl));
        if (lc == 0)
            g_stats[(size_t)bh*TGT + q] = make_float2(m_r[hf], invl);
    }
}

// ===========================================================================
// avg weights: 256 thr, block 128(q) x 64(k), warp tile 32x32,
// cp.async + double-buffered Q/K across the head loop.
// SMEM floats: Q0@0(9216) Q1@9216 K0@18432(4608) K1@23040 -> 27648 (110592 B)
// ===========================================================================
#define AVG_SMEM_BYTES (27648*4)

__global__ __launch_bounds__(256)
void avg_attn_k(float* __restrict__ avg_out)
{
    extern __shared__ float sm[];
    const uint32_t sb = smem_u32(sm);
    const int tid = threadIdx.x, lane = tid & 31, wid = tid >> 5;
    const int wm = wid & 3, wn = wid >> 2;          // 4(q) x 2(k)
    const int lr = lane >> 2, lc = lane & 3;
    const int kt = blockIdx.x, qt = blockIdx.y, b = blockIdx.z;

    auto issue_qk = [&](int h){
        const int buf = h & 1;
        const int bh = b*NH + h;
        const float* Qg = g_Q + (size_t)bh*TGT*HD;
        const float* Kg = g_K + (size_t)bh*TGT*HD;
        const uint32_t qb = sb + (buf*9216)*4;
        const uint32_t kb = sb + (18432 + buf*4608)*4;
        #pragma unroll
        for (int i=0;i<8;i++){
            int fi = tid + i*256, r = fi>>4, c4 = fi&15;
            cpa16(qb + ((c4>=8)*4608 + r*36 + (c4&7)*4)*4,
                  Qg + (size_t)(qt*128+r)*HD + c4*4);
        }
        #pragma unroll
        for (int i=0;i<4;i++){
            int fi = tid + i*256, r = fi>>4, c4 = fi&15;
            cpa16(kb + ((c4>=8)*2304 + r*36 + (c4&7)*4)*4,
                  Kg + (size_t)(kt*64+r)*HD + c4*4);
        }
        CP_COMMIT();
    };

    float acc[2][4][4];
    #pragma unroll
    for (int i=0;i<2;i++) for (int j=0;j<4;j++) for (int k=0;k<4;k++) acc[i][j][k]=0.f;

    issue_qk(0);
    for (int h = 0; h < NH; h++) {
        if (h + 1 < NH) { issue_qk(h+1); CP_WAIT(1); } else { CP_WAIT(0); }
        __syncthreads();
        const float* QB = sm + (h&1)*9216;
        const float* KB = sm + 18432 + (h&1)*4608;

        float s[2][4][4];
        #pragma unroll
        for (int i=0;i<2;i++) for (int j=0;j<4;j++) for (int k=0;k<4;k++) s[i][j][k]=0.f;
        #pragma unroll
        for (int ks=0; ks<8; ks++){
            const int hb = ks>>2, ko = (ks&3)*8;
            uint32_t af[2][4], bf[4][2];
            #pragma unroll
            for (int mt=0; mt<2; mt++){
                const float* p = QB + hb*4608 + (wm*32 + mt*16 + lr)*36 + ko + lc;
                af[mt][0]=__float_as_uint(p[0]); af[mt][1]=__float_as_uint(p[8*36]);
                af[mt][2]=__float_as_uint(p[4]); af[mt][3]=__float_as_uint(p[8*36+4]);
            }
            #pragma unroll
            for (int nt=0; nt<4; nt++){
                const float* p = KB + hb*2304 + (wn*32 + nt*8 + lr)*36 + ko + lc;
                bf[nt][0]=__float_as_uint(p[0]); bf[nt][1]=__float_as_uint(p[4]);
            }
            #pragma unroll
            for (int mt=0; mt<2; mt++)
                #pragma unroll
                for (int nt=0; nt<4; nt++)
                    mma8(s[mt][nt], af[mt], bf[nt]);
        }

        const int bh = b*NH + h;
        #pragma unroll
        for (int mt=0; mt<2; mt++)
        #pragma unroll
        for (int hf=0; hf<2; hf++){
            const int q = qt*128 + wm*32 + mt*16 + hf*8 + lr;
            const float2 st = g_stats[(size_t)bh*TGT + q];
            #pragma unroll
            for (int nt=0; nt<4; nt++){
                acc[mt][nt][hf*2]   += __expf(s[mt][nt][hf*2]   - st.x) * st.y;
                acc[mt][nt][hf*2+1] += __expf(s[mt][nt][hf*2+1] - st.x) * st.y;
            }
        }
        __syncthreads();
    }

    const float invH = 1.0f / NH;
    #pragma unroll
    for (int mt=0; mt<2; mt++)
    #pragma unroll
    for (int hf=0; hf<2; hf++){
        const int q = qt*128 + wm*32 + mt*16 + hf*8 + lr;
        float* dst = avg_out + ((size_t)b*TGT + q)*TGT + kt*64 + wn*32;
        #pragma unroll
        for (int nt=0; nt<4; nt++)
            *(float2*)(dst + nt*8 + lc*2) =
                make_float2(acc[mt][nt][hf*2]*invH, acc[mt][nt][hf*2+1]*invH);
    }
}

// ---------------------------------------------------------------------------
extern "C" void kernel_launch(void* const* d_in, const int* in_sizes, int n_in,
                              void* d_out, int out_size)
{
    const float* query = (const float*)d_in[0];
    const float* w_in  = (const float*)d_in[1];
    const float* b_in  = (const float*)d_in[2];
    const float* w_out = (const float*)d_in[3];
    const float* b_out = (const float*)d_in[4];

    float* out      = (float*)d_out;
    float* attn_out = out;                           // [T,B,E]
    float* avg_out  = out + (size_t)TGT*NBSZ*EMB;    // [B,T,T]

    cudaFuncSetAttribute(mma_gemm<0>,  cudaFuncAttributeMaxDynamicSharedMemorySize, GEMM_SMEM_BYTES);
    cudaFuncSetAttribute(mma_gemm<3>,  cudaFuncAttributeMaxDynamicSharedMemorySize, GEMM_SMEM_BYTES);
    cudaFuncSetAttribute(flash_attn_k, cudaFuncAttributeMaxDynamicSharedMemorySize, FA_SMEM_BYTES);
    cudaFuncSetAttribute(avg_attn_k,   cudaFuncAttributeMaxDynamicSharedMemorySize, AVG_SMEM_BYTES);

    float* d_qc;  cudaGetSymbolAddress((void**)&d_qc,  g_qc);
    float* d_wic; cudaGetSymbolAddress((void**)&d_wic, g_wic);
    float* d_woc; cudaGetSymbolAddress((void**)&d_woc, g_woc);

    // 0. pre-round inputs to tf32
    {
        int n4q = MROWS*EMB/4, n4wi = 3*EMB*EMB/4, n4wo = EMB*EMB/4;
        preround_k<<<(n4q +255)/256, 256>>>((const float4*)query, (float4*)d_qc,  n4q);
        preround_k<<<(n4wi+255)/256, 256>>>((const float4*)w_in,  (float4*)d_wic, n4wi);
        preround_k<<<(n4wo+255)/256, 256>>>((const float4*)w_out, (float4*)d_woc, n4wo);
    }

    // 1. QKV projection (warp tile 64x64, cp.async)
    mma_gemm<0><<<dim3(3*EMB/128, MROWS/256), 256, GEMM_SMEM_BYTES>>>(nullptr, b_in);

    // 2. Flash attention (double-buffered K/V)
    flash_attn_k<<<dim3(TGT/128, NBH), 256, FA_SMEM_BYTES>>>();

    // 3. Averaged attention weights (double-buffered Q/K over heads)
    avg_attn_k<<<dim3(TGT/64, TGT/128, NBSZ), 256, AVG_SMEM_BYTES>>>(avg_out);

    // 4. Output projection
    mma_gemm<3><<<dim3(EMB/128, MROWS/256), 256, GEMM_SMEM_BYTES>>>(attn_out, b_out);
}